// round 15
// baseline (speedup 1.0000x reference)
#include <cuda_runtime.h>
#include <cuda_fp16.h>
#include <cstdint>

#define T_  512
#define B_  128
#define I_  512
#define H_  1024
#define NG  4096
#define KZ  1536
#define SCAN_BLOCKS  128
#define GX_WORKERS   20
#define FUSED_BLOCKS (SCAN_BLOCKS + GX_WORKERS)
#define SCAN_THREADS 512

__device__ __half g_xh[(size_t)T_ * B_ * I_];
__device__ __half g_gx[(size_t)T_ * B_ * NG];
__device__ __half g_Wh[(size_t)NG * H_];
__device__ __half g_Wx[(size_t)NG * I_];
// h ping-pong, k-chunked + padded rows: [buf][kchunk][row][136]
__device__ __align__(1024) __half g_hk[2][8][128][136];
__device__ int g_done[SCAN_BLOCKS];
__device__ int gx_done[T_];          // per-timestep finished N-tiles (32 = ready)

__device__ __forceinline__ float sigm(float x) { return 1.0f / (1.0f + __expf(-x)); }
__device__ __forceinline__ float tanh_fast(float x) {
    float e = __expf(-2.0f * fabsf(x));
    return copysignf((1.0f - e) / (1.0f + e), x);
}
__device__ __forceinline__ void mma16816(float* d, const uint32_t* a, uint32_t b0, uint32_t b1) {
    asm volatile(
        "mma.sync.aligned.m16n8k16.row.col.f32.f16.f16.f32 "
        "{%0,%1,%2,%3}, {%4,%5,%6,%7}, {%8,%9}, {%0,%1,%2,%3};\n"
        : "+f"(d[0]), "+f"(d[1]), "+f"(d[2]), "+f"(d[3])
        : "r"(a[0]), "r"(a[1]), "r"(a[2]), "r"(a[3]), "r"(b0), "r"(b1));
}
__device__ __forceinline__ void ldsm_x4(uint32_t* r, uint32_t addr) {
    asm volatile("ldmatrix.sync.aligned.m8n8.x4.shared.b16 {%0,%1,%2,%3}, [%4];"
                 : "=r"(r[0]), "=r"(r[1]), "=r"(r[2]), "=r"(r[3]) : "r"(addr));
}
__device__ __forceinline__ int ld_acquire_gpu(const int* p) {
    int v; asm volatile("ld.acquire.gpu.b32 %0, [%1];\n" : "=r"(v) : "l"(p) : "memory"); return v;
}
__device__ __forceinline__ void st_release_gpu(int* p, int v) {
    asm volatile("st.release.gpu.global.b32 [%0], %1;\n" :: "l"(p), "r"(v) : "memory");
}
__device__ __forceinline__ void red_release_add(int* p, int v) {
    asm volatile("red.release.gpu.global.add.s32 [%0], %1;\n" :: "l"(p), "r"(v) : "memory");
}
__device__ __forceinline__ uint32_t smem_u32(const void* p) {
    uint32_t a; asm("{ .reg .u64 t; cvta.to.shared.u64 t, %1; cvt.u32.u64 %0, t; }" : "=r"(a) : "l"(p)); return a;
}
__device__ __forceinline__ void mbar_init(uint32_t m, uint32_t c) {
    asm volatile("mbarrier.init.shared.b64 [%0], %1;" :: "r"(m), "r"(c) : "memory");
}
__device__ __forceinline__ void mbar_expect_tx(uint32_t m, uint32_t bytes) {
    asm volatile("mbarrier.arrive.expect_tx.shared.b64 _, [%0], %1;" :: "r"(m), "r"(bytes) : "memory");
}
__device__ __forceinline__ void mbar_wait(uint32_t m, uint32_t par) {
    asm volatile(
        "{\n\t.reg .pred P1;\n\t"
        "WL_%=:\n\t"
        "mbarrier.try_wait.parity.shared.b64 P1, [%0], %1;\n\t"
        "@P1 bra.uni WD_%=;\n\tbra.uni WL_%=;\n\tWD_%=:\n\t}"
        :: "r"(m), "r"(par) : "memory");
}
__device__ __forceinline__ void bulk_g2s(uint32_t dst, const void* src, uint32_t bytes, uint32_t mbar) {
    asm volatile("cp.async.bulk.shared::cluster.global.mbarrier::complete_tx::bytes [%0], [%1], %2, [%3];"
                 :: "r"(dst), "l"(src), "r"(bytes), "r"(mbar) : "memory");
}
__device__ __forceinline__ void cp_async16(uint32_t s, const void* g) {
    asm volatile("cp.async.cg.shared.global [%0], [%1], 16;\n" :: "r"(s), "l"(g));
}
__device__ __forceinline__ void fence_pa() { asm volatile("fence.proxy.async.shared::cta;" ::: "memory"); }

// ---------------- prep ----------------------------------------------------
__global__ void k_prep_weights(const float* __restrict__ Wf, const float* __restrict__ Wi,
                               const float* __restrict__ Wc, const float* __restrict__ Wo) {
    size_t idx = (size_t)blockIdx.x * blockDim.x + threadIdx.x;
    if (idx < (size_t)NG * KZ) {
        int n = (int)(idx / KZ), k = (int)(idx % KZ);
        int g = n >> 10, j = n & 1023;
        const float* W = (g == 0) ? Wf : (g == 1) ? Wi : (g == 2) ? Wc : Wo;
        float v = W[(size_t)j * KZ + k];
        if (k < H_) g_Wh[(size_t)n * H_ + k]        = __float2half(v);
        else        g_Wx[(size_t)n * I_ + (k - H_)] = __float2half(v);
    }
    if (idx < (size_t)2 * 8 * 128 * 136) ((__half*)g_hk)[idx] = __float2half(0.0f);
    if (idx < SCAN_BLOCKS) g_done[idx] = 0;
    if (idx < T_) gx_done[idx] = 0;
}

__global__ void k_convert_x(const float* __restrict__ x) {
    size_t idx = (size_t)blockIdx.x * blockDim.x + threadIdx.x;
    if (idx < (size_t)T_ * B_ * I_) g_xh[idx] = __float2half(x[idx]);
}

// ---------------- fused kernel constants -------------------------------------
#define HS_LD 136
#define CHKB  (64 * HS_LD * 2)       // 17408 bytes per chunk
#define WS_LD 1032
#define WS_HALFS (64 * WS_LD)
#define WS_BYTES (WS_HALFS * 2)      // 132096
#define SCAN_SMEM (WS_BYTES + 4 * CHKB)

// ---------------- gx worker: time-major pipelined GEMM tiles -----------------
// 512 threads, warp grid 4m x 4n, warp tile 32x32. cp.async double buffer.
// Worker wkr handles tiles id = wkr, wkr+GX_WORKERS, ... ; id = t*32 + ntile.
__device__ void gx_worker(int wkr, char* smemraw,
                          const float* __restrict__ bf, const float* __restrict__ bi,
                          const float* __restrict__ bc, const float* __restrict__ bo) {
    typedef __half (*TileP)[128][40];
    TileP As = (TileP)smemraw;                       // [2][128][40]
    TileP Bs = (TileP)(smemraw + 2 * 128 * 40 * 2);  // [2][128][40]

    const int tid = threadIdx.x, w = tid >> 5, lane = tid & 31;
    const int gid = lane >> 2, t4 = lane & 3;
    const int wm = w >> 2, wn = w & 3;

    const uint32_t as_base = smem_u32(&As[0][0][0]);
    const uint32_t bs_base = smem_u32(&Bs[0][0][0]);
    const uint32_t buf_stride = 128 * 40 * 2;

    const int r0 = tid >> 2, c0 = tid & 3;           // one 16B chunk per thread per array

    for (int id = wkr; id < T_ * 32; id += GX_WORKERS) {
        const int t  = id >> 5;
        const int m0 = t * 128;
        const int n0 = (id & 31) * 128;

        float acc[2][4][4];
#pragma unroll
        for (int mt = 0; mt < 2; mt++)
#pragma unroll
            for (int nt = 0; nt < 4; nt++)
#pragma unroll
                for (int e = 0; e < 4; e++) acc[mt][nt][e] = 0.0f;

        // prefetch stage 0
        cp_async16(as_base + (uint32_t)((r0 * 40 + c0 * 8) * 2), &g_xh[(size_t)(m0 + r0) * I_ + c0 * 8]);
        cp_async16(bs_base + (uint32_t)((r0 * 40 + c0 * 8) * 2), &g_Wx[(size_t)(n0 + r0) * I_ + c0 * 8]);
        asm volatile("cp.async.commit_group;\n");

#pragma unroll 1
        for (int s = 0; s < 16; s++) {
            if (s < 15) {
                const int kb = (s + 1) * 32;
                const uint32_t bo_ = (uint32_t)(((s + 1) & 1) * buf_stride);
                cp_async16(as_base + bo_ + (uint32_t)((r0 * 40 + c0 * 8) * 2),
                           &g_xh[(size_t)(m0 + r0) * I_ + kb + c0 * 8]);
                cp_async16(bs_base + bo_ + (uint32_t)((r0 * 40 + c0 * 8) * 2),
                           &g_Wx[(size_t)(n0 + r0) * I_ + kb + c0 * 8]);
                asm volatile("cp.async.commit_group;\n");
                asm volatile("cp.async.wait_group 1;\n");
            } else {
                asm volatile("cp.async.wait_group 0;\n");
            }
            __syncthreads();

            const int bi_ = s & 1;
#pragma unroll
            for (int ks = 0; ks < 2; ks++) {
                const int ko = ks * 16;
                uint32_t a[2][4], b[4][2];
#pragma unroll
                for (int mt = 0; mt < 2; mt++) {
                    int r = wm * 32 + mt * 16 + gid;
                    a[mt][0] = *(const uint32_t*)&As[bi_][r][ko + t4 * 2];
                    a[mt][1] = *(const uint32_t*)&As[bi_][r + 8][ko + t4 * 2];
                    a[mt][2] = *(const uint32_t*)&As[bi_][r][ko + t4 * 2 + 8];
                    a[mt][3] = *(const uint32_t*)&As[bi_][r + 8][ko + t4 * 2 + 8];
                }
#pragma unroll
                for (int nt = 0; nt < 4; nt++) {
                    int c = wn * 32 + nt * 8 + gid;
                    b[nt][0] = *(const uint32_t*)&Bs[bi_][c][ko + t4 * 2];
                    b[nt][1] = *(const uint32_t*)&Bs[bi_][c][ko + t4 * 2 + 8];
                }
#pragma unroll
                for (int mt = 0; mt < 2; mt++)
#pragma unroll
                    for (int nt = 0; nt < 4; nt++)
                        mma16816(acc[mt][nt], a[mt], b[nt][0], b[nt][1]);
            }
            __syncthreads();
        }

        // epilogue: add bias, store fp16
#pragma unroll
        for (int nt = 0; nt < 4; nt++) {
            int n = n0 + wn * 32 + nt * 8 + t4 * 2;
            int g = n >> 10, j = n & 1023;
            const float* bias = (g == 0) ? bf : (g == 1) ? bi : (g == 2) ? bc : bo;
            float b0 = bias[j], b1 = bias[j + 1];
#pragma unroll
            for (int mt = 0; mt < 2; mt++) {
                int m = m0 + wm * 32 + mt * 16 + gid;
                *(__half2*)&g_gx[(size_t)m * NG + n]       = __floats2half2_rn(acc[mt][nt][0] + b0, acc[mt][nt][1] + b1);
                *(__half2*)&g_gx[(size_t)(m + 8) * NG + n] = __floats2half2_rn(acc[mt][nt][2] + b0, acc[mt][nt][3] + b1);
            }
        }
        __syncthreads();                  // all 512 threads' stores issued
        if (tid == 0) red_release_add(&gx_done[t], 1);
    }
}

// ---------------- fused persistent kernel ------------------------------------
// Blocks 0..127: LSTM scan (R14 structure). Blocks 128..147: gx workers.
__global__ __launch_bounds__(SCAN_THREADS, 1) void k_scan(float* __restrict__ out,
                                                          const float* __restrict__ bf,
                                                          const float* __restrict__ bi,
                                                          const float* __restrict__ bc,
                                                          const float* __restrict__ bo) {
    extern __shared__ __half sm[];

    if (blockIdx.x >= SCAN_BLOCKS) {
        gx_worker(blockIdx.x - SCAN_BLOCKS, (char*)sm, bf, bi, bc, bo);
        return;
    }

    __half* ws = sm;                 // [64][WS_LD], row = g*16 + jl
    __half* hs = sm + WS_HALFS;      // 4 buffers [64][HS_LD]; reused as reduce scratch
    __shared__ __align__(8) uint64_t s_mbar[4];

    const int tid  = threadIdx.x;
    const int w    = tid >> 5;
    const int lane = tid & 31;
    const int kg   = w >> 3;         // group 0/1 (tids 0-255 / 256-511)
    const int ww   = w & 7;
    const int wm   = ww >> 1;        // 0..3 m-tile
    const int wn   = ww & 1;         // 0..1 j-half
    const int gid  = lane >> 2;
    const int t4   = lane & 3;

    const int bid   = blockIdx.x;
    const int mhalf = bid & 1;
    const int jb    = bid >> 1;
    const int j0    = jb * 16;

    // ---- Wh slice once: row r = g*16+jl ----
#pragma unroll 4
    for (int i = 0; i < 16; i++) {
        int cid = tid + i * SCAN_THREADS;
        int r = cid >> 7, ch = cid & 127;
        int g = r >> 4, jl = r & 15;
        *(uint4*)&ws[r * WS_LD + ch * 8] =
            *(const uint4*)&g_Wh[(size_t)(g * H_ + j0 + jl) * H_ + ch * 8];
    }

    const uint32_t hs_base = smem_u32(hs);
    const uint32_t ws_base = smem_u32(ws);
    uint32_t mb[4];
#pragma unroll
    for (int i = 0; i < 4; i++) mb[i] = smem_u32(&s_mbar[i]);
    if (tid == 0) {
#pragma unroll
        for (int i = 0; i < 4; i++) mbar_init(mb[i], 1);
        fence_pa();
    }
    __syncthreads();

    // ldmatrix lane addresses (bytes)
    const int a_row = wm * 16 + ((lane >> 3) & 1) * 8 + (lane & 7);
    const uint32_t a_lane_off = (uint32_t)((a_row * HS_LD + (lane >> 4) * 8) * 2);
    const uint32_t b_lane0 = ws_base + (uint32_t)(((((lane >> 4) + 0) * 16 + wn * 8 + (lane & 7)) * WS_LD
                                                   + ((lane >> 3) & 1) * 8) * 2);
    const uint32_t b_lane1 = ws_base + (uint32_t)(((((lane >> 4) + 2) * 16 + wn * 8 + (lane & 7)) * WS_LD
                                                   + ((lane >> 3) & 1) * 8) * 2);

    const int my_r = wm * 16 + gid;
    const int my_j = j0 + wn * 8 + t4 * 2;

    float cst[4] = {0.f, 0.f, 0.f, 0.f};    // kg0 warps only

    for (int t = 0; t < T_; t++) {
        const int hbuf = t & 1;

        // gx gate + prefetch (epilogue threads; gx_done[t]==32 means tile row ready)
        uint4 gq[8];
        if (tid < 256) {
            while (ld_acquire_gpu(&gx_done[t]) < 32) {}
            const __half* gp = &g_gx[((size_t)t * B_ + mhalf * 64 + my_r) * NG + my_j];
#pragma unroll
            for (int g = 0; g < 4; g++) {
                gq[g]     = __ldg((const uint4*)((const char*)gp + (size_t)g * H_ * 2 - (my_j & 7) * 2));
                gq[4 + g] = __ldg((const uint4*)((const char*)(gp + 8 * NG) + (size_t)g * H_ * 2 - (my_j & 7) * 2));
            }
        }

        if (t > 0) {
            if (tid < 64) {
                const int* p = &g_done[mhalf + 2 * tid];
                while (ld_acquire_gpu(p) < t) {}
            }
            __syncthreads();
        }

        // first wave: chunks 0..3 into buffers 0..3
        if (tid == 0) {
#pragma unroll
            for (int c = 0; c < 4; c++) {
                mbar_expect_tx(mb[c], CHKB);
                bulk_g2s(hs_base + (uint32_t)(c * CHKB), &g_hk[hbuf][c][mhalf * 64][0], CHKB, mb[c]);
            }
        }

        float acc[4][4];
#pragma unroll
        for (int g = 0; g < 4; g++)
#pragma unroll
            for (int e = 0; e < 4; e++) acc[g][e] = 0.f;

        // ---- group-local pipeline: 4 chunks, 2 buffers ----
#pragma unroll
        for (int i = 0; i < 4; i++) {
            const int c = kg + 2 * i;                 // my chunk
            const int b = kg + ((i & 1) << 1);        // its buffer
            mbar_wait(mb[b], (uint32_t)(i >> 1));     // parities 0,0,1,1

            const uint32_t aA  = hs_base + (uint32_t)(b * CHKB) + a_lane_off;
            const uint32_t aB0 = b_lane0 + (uint32_t)(c * 256);
            const uint32_t aB1 = b_lane1 + (uint32_t)(c * 256);
#pragma unroll
            for (int ks = 0; ks < 8; ks++) {
                uint32_t a[4], b01[4], b23[4];
                ldsm_x4(a,   aA  + ks * 32);
                ldsm_x4(b01, aB0 + ks * 32);
                ldsm_x4(b23, aB1 + ks * 32);
                mma16816(acc[0], a, b01[0], b01[1]);
                mma16816(acc[1], a, b01[2], b01[3]);
                mma16816(acc[2], a, b23[0], b23[1]);
                mma16816(acc[3], a, b23[2], b23[3]);
            }
            // group-local barrier: my 8 warps done reading buffer b
            asm volatile("bar.sync %0, 256;" :: "r"(kg + 1) : "memory");
            if (i < 2 && ww == 0 && lane == 0) {
                mbar_expect_tx(mb[b], CHKB);
                bulk_g2s(hs_base + (uint32_t)(b * CHKB),
                         &g_hk[hbuf][c + 4][mhalf * 64][0], CHKB, mb[b]);
            }
        }
        __syncthreads();   // both groups done with all buffers (scratch reuse below)

        // ---- merge k-halves via SMEM (stride 20 floats) ----
        float* red = (float*)hs;
        const int rb = (ww * 32 + lane) * 20;
        if (kg == 1) {
#pragma unroll
            for (int g = 0; g < 4; g++)
                *(float4*)&red[rb + g * 4] = make_float4(acc[g][0], acc[g][1], acc[g][2], acc[g][3]);
        }
        __syncthreads();

        if (kg == 0) {
#pragma unroll
            for (int g = 0; g < 4; g++) {
                float4 v = *(const float4*)&red[rb + g * 4];
                acc[g][0] += v.x; acc[g][1] += v.y; acc[g][2] += v.z; acc[g][3] += v.w;
            }
            const int jc  = my_j >> 7;
            const int jcc = my_j & 127;
            const __half* gxh = (const __half*)gq;
            const int lo = my_j & 7;
#pragma unroll
            for (int rr = 0; rr < 2; rr++) {
                const int b_row = mhalf * 64 + my_r + rr * 8;
                float hres[2];
#pragma unroll
                for (int cc = 0; cc < 2; cc++) {
                    const int ai = rr * 2 + cc;
                    float pf = acc[0][ai] + __half2float(gxh[(rr * 4 + 0) * 8 + lo + cc]);
                    float pi = acc[1][ai] + __half2float(gxh[(rr * 4 + 1) * 8 + lo + cc]);
                    float pc = acc[2][ai] + __half2float(gxh[(rr * 4 + 2) * 8 + lo + cc]);
                    float po = acc[3][ai] + __half2float(gxh[(rr * 4 + 3) * 8 + lo + cc]);
                    float f = sigm(pf), ii = sigm(pi), ct = tanh_fast(pc), o = sigm(po);
                    float cn = f * cst[ai] + ii * ct;
                    cst[ai] = cn;
                    hres[cc] = o * tanh_fast(cn);
                }
                *(float2*)&out[((size_t)t * B_ + b_row) * H_ + my_j] = make_float2(hres[0], hres[1]);
                *(__half2*)&g_hk[hbuf ^ 1][jc][b_row][jcc] = __floats2half2_rn(hres[0], hres[1]);
            }
        }

        __syncthreads();
        if (tid == 0) st_release_gpu(&g_done[bid], t + 1);
    }
}

// ---------------- launch ----------------------------------------------------
extern "C" void kernel_launch(void* const* d_in, const int* in_sizes, int n_in,
                              void* d_out, int out_size) {
    const float* x  = (const float*)d_in[0];
    const float* Wf = (const float*)d_in[1];
    const float* bf = (const float*)d_in[2];
    const float* Wi = (const float*)d_in[3];
    const float* bi = (const float*)d_in[4];
    const float* Wc = (const float*)d_in[5];
    const float* bc = (const float*)d_in[6];
    const float* Wo = (const float*)d_in[7];
    const float* bo = (const float*)d_in[8];
    float* out = (float*)d_out;

    cudaFuncSetAttribute(k_scan, cudaFuncAttributeMaxDynamicSharedMemorySize, SCAN_SMEM);

    {
        size_t total = (size_t)NG * KZ;
        k_prep_weights<<<(int)((total + 255) / 256), 256>>>(Wf, Wi, Wc, Wo);
    }
    {
        size_t total = (size_t)T_ * B_ * I_;
        k_convert_x<<<(int)((total + 255) / 256), 256>>>(x);
    }

    k_scan<<<FUSED_BLOCKS, SCAN_THREADS, SCAN_SMEM>>>(out, bf, bi, bc, bo);
}

// round 16
// speedup vs baseline: 2.0213x; 2.0213x over previous
#include <cuda_runtime.h>
#include <cuda_fp16.h>
#include <cstdint>

#define T_  512
#define B_  128
#define I_  512
#define H_  1024
#define NG  4096
#define KZ  1536
#define SCAN_BLOCKS  128
#define SCAN_THREADS 544            // 16 compute warps + 1 copy warp

__device__ __half g_xh[(size_t)T_ * B_ * I_];
__device__ __half g_gx[(size_t)T_ * B_ * NG];
__device__ __half g_Wh[(size_t)NG * H_];
__device__ __half g_Wx[(size_t)NG * I_];
// h ping-pong, k-chunked + padded rows: [buf][kchunk][row][136]
__device__ __align__(1024) __half g_hk[2][8][128][136];
__device__ int g_cnt[16];            // [kchunk][mhalf] monotonic producer counters

__device__ __forceinline__ float sigm(float x) { return 1.0f / (1.0f + __expf(-x)); }
__device__ __forceinline__ float tanh_fast(float x) {
    float e = __expf(-2.0f * fabsf(x));
    return copysignf((1.0f - e) / (1.0f + e), x);
}
__device__ __forceinline__ void mma16816(float* d, const uint32_t* a, uint32_t b0, uint32_t b1) {
    asm volatile(
        "mma.sync.aligned.m16n8k16.row.col.f32.f16.f16.f32 "
        "{%0,%1,%2,%3}, {%4,%5,%6,%7}, {%8,%9}, {%0,%1,%2,%3};\n"
        : "+f"(d[0]), "+f"(d[1]), "+f"(d[2]), "+f"(d[3])
        : "r"(a[0]), "r"(a[1]), "r"(a[2]), "r"(a[3]), "r"(b0), "r"(b1));
}
__device__ __forceinline__ void ldsm_x4(uint32_t* r, uint32_t addr) {
    asm volatile("ldmatrix.sync.aligned.m8n8.x4.shared.b16 {%0,%1,%2,%3}, [%4];"
                 : "=r"(r[0]), "=r"(r[1]), "=r"(r[2]), "=r"(r[3]) : "r"(addr));
}
__device__ __forceinline__ int ld_acquire_gpu(const int* p) {
    int v; asm volatile("ld.acquire.gpu.b32 %0, [%1];\n" : "=r"(v) : "l"(p) : "memory"); return v;
}
__device__ __forceinline__ void red_release_add(int* p, int v) {
    asm volatile("red.release.gpu.global.add.s32 [%0], %1;\n" :: "l"(p), "r"(v) : "memory");
}
__device__ __forceinline__ uint32_t smem_u32(const void* p) {
    uint32_t a; asm("{ .reg .u64 t; cvta.to.shared.u64 t, %1; cvt.u32.u64 %0, t; }" : "=r"(a) : "l"(p)); return a;
}
__device__ __forceinline__ void mbar_init(uint32_t m, uint32_t c) {
    asm volatile("mbarrier.init.shared.b64 [%0], %1;" :: "r"(m), "r"(c) : "memory");
}
__device__ __forceinline__ void mbar_expect_tx(uint32_t m, uint32_t bytes) {
    asm volatile("mbarrier.arrive.expect_tx.shared.b64 _, [%0], %1;" :: "r"(m), "r"(bytes) : "memory");
}
__device__ __forceinline__ void mbar_arrive(uint32_t m) {
    asm volatile("mbarrier.arrive.shared.b64 _, [%0];" :: "r"(m) : "memory");
}
__device__ __forceinline__ void mbar_wait(uint32_t m, uint32_t par) {
    asm volatile(
        "{\n\t.reg .pred P1;\n\t"
        "WL_%=:\n\t"
        "mbarrier.try_wait.parity.shared.b64 P1, [%0], %1;\n\t"
        "@P1 bra.uni WD_%=;\n\tbra.uni WL_%=;\n\tWD_%=:\n\t}"
        :: "r"(m), "r"(par) : "memory");
}
__device__ __forceinline__ void bulk_g2s(uint32_t dst, const void* src, uint32_t bytes, uint32_t mbar) {
    asm volatile("cp.async.bulk.shared::cluster.global.mbarrier::complete_tx::bytes [%0], [%1], %2, [%3];"
                 :: "r"(dst), "l"(src), "r"(bytes), "r"(mbar) : "memory");
}
__device__ __forceinline__ void cp_async16(uint32_t s, const void* g) {
    asm volatile("cp.async.cg.shared.global [%0], [%1], 16;\n" :: "r"(s), "l"(g));
}
__device__ __forceinline__ void fence_pa() { asm volatile("fence.proxy.async.shared::cta;" ::: "memory"); }

// ---------------- prep ----------------------------------------------------
__global__ void k_prep_weights(const float* __restrict__ Wf, const float* __restrict__ Wi,
                               const float* __restrict__ Wc, const float* __restrict__ Wo) {
    size_t idx = (size_t)blockIdx.x * blockDim.x + threadIdx.x;
    if (idx < (size_t)NG * KZ) {
        int n = (int)(idx / KZ), k = (int)(idx % KZ);
        int g = n >> 10, j = n & 1023;
        const float* W = (g == 0) ? Wf : (g == 1) ? Wi : (g == 2) ? Wc : Wo;
        float v = W[(size_t)j * KZ + k];
        if (k < H_) g_Wh[(size_t)n * H_ + k]        = __float2half(v);
        else        g_Wx[(size_t)n * I_ + (k - H_)] = __float2half(v);
    }
    if (idx < (size_t)2 * 8 * 128 * 136) ((__half*)g_hk)[idx] = __float2half(0.0f);
    if (idx < 16) g_cnt[idx] = 0;
}

__global__ void k_convert_x(const float* __restrict__ x) {
    size_t idx = (size_t)blockIdx.x * blockDim.x + threadIdx.x;
    if (idx < (size_t)T_ * B_ * I_) g_xh[idx] = __float2half(x[idx]);
}

// ---------------- gx GEMM: cp.async double-buffered (R14, passing) ----------
__global__ __launch_bounds__(256) void k_gx(const float* __restrict__ bf, const float* __restrict__ bi,
                                            const float* __restrict__ bc, const float* __restrict__ bo) {
    __shared__ __half As[2][128][40];
    __shared__ __half Bs[2][128][40];
    const int m0 = blockIdx.y * 128, n0 = blockIdx.x * 128;
    const int tid = threadIdx.x, w = tid >> 5, lane = tid & 31;
    const int gid = lane >> 2, t4 = lane & 3, wm = w >> 1, wn = w & 1;

    const uint32_t as_base = smem_u32(&As[0][0][0]);
    const uint32_t bs_base = smem_u32(&Bs[0][0][0]);
    const uint32_t buf_stride = 128 * 40 * 2;

    float acc[2][8][4];
#pragma unroll
    for (int mt = 0; mt < 2; mt++)
#pragma unroll
        for (int nt = 0; nt < 8; nt++)
#pragma unroll
            for (int e = 0; e < 4; e++) acc[mt][nt][e] = 0.0f;

    const int r0 = tid >> 2, c0 = tid & 3;
    const int r1 = (tid + 256) >> 2, c1 = (tid + 256) & 3;

    cp_async16(as_base + (uint32_t)((r0 * 40 + c0 * 8) * 2), &g_xh[(size_t)(m0 + r0) * I_ + c0 * 8]);
    cp_async16(as_base + (uint32_t)((r1 * 40 + c1 * 8) * 2), &g_xh[(size_t)(m0 + r1) * I_ + c1 * 8]);
    cp_async16(bs_base + (uint32_t)((r0 * 40 + c0 * 8) * 2), &g_Wx[(size_t)(n0 + r0) * I_ + c0 * 8]);
    cp_async16(bs_base + (uint32_t)((r1 * 40 + c1 * 8) * 2), &g_Wx[(size_t)(n0 + r1) * I_ + c1 * 8]);
    asm volatile("cp.async.commit_group;\n");

#pragma unroll 1
    for (int s = 0; s < 16; s++) {
        if (s < 15) {
            const int kb = (s + 1) * 32;
            const uint32_t bo_ = (uint32_t)(((s + 1) & 1) * buf_stride);
            cp_async16(as_base + bo_ + (uint32_t)((r0 * 40 + c0 * 8) * 2), &g_xh[(size_t)(m0 + r0) * I_ + kb + c0 * 8]);
            cp_async16(as_base + bo_ + (uint32_t)((r1 * 40 + c1 * 8) * 2), &g_xh[(size_t)(m0 + r1) * I_ + kb + c1 * 8]);
            cp_async16(bs_base + bo_ + (uint32_t)((r0 * 40 + c0 * 8) * 2), &g_Wx[(size_t)(n0 + r0) * I_ + kb + c0 * 8]);
            cp_async16(bs_base + bo_ + (uint32_t)((r1 * 40 + c1 * 8) * 2), &g_Wx[(size_t)(n0 + r1) * I_ + kb + c1 * 8]);
            asm volatile("cp.async.commit_group;\n");
            asm volatile("cp.async.wait_group 1;\n");
        } else {
            asm volatile("cp.async.wait_group 0;\n");
        }
        __syncthreads();

        const int bi_ = s & 1;
#pragma unroll
        for (int ks = 0; ks < 2; ks++) {
            const int ko = ks * 16;
            uint32_t a[2][4], b[8][2];
#pragma unroll
            for (int mt = 0; mt < 2; mt++) {
                int r = wm * 32 + mt * 16 + gid;
                a[mt][0] = *(const uint32_t*)&As[bi_][r][ko + t4 * 2];
                a[mt][1] = *(const uint32_t*)&As[bi_][r + 8][ko + t4 * 2];
                a[mt][2] = *(const uint32_t*)&As[bi_][r][ko + t4 * 2 + 8];
                a[mt][3] = *(const uint32_t*)&As[bi_][r + 8][ko + t4 * 2 + 8];
            }
#pragma unroll
            for (int nt = 0; nt < 8; nt++) {
                int c = wn * 64 + nt * 8 + gid;
                b[nt][0] = *(const uint32_t*)&Bs[bi_][c][ko + t4 * 2];
                b[nt][1] = *(const uint32_t*)&Bs[bi_][c][ko + t4 * 2 + 8];
            }
#pragma unroll
            for (int mt = 0; mt < 2; mt++)
#pragma unroll
                for (int nt = 0; nt < 8; nt++)
                    mma16816(acc[mt][nt], a[mt], b[nt][0], b[nt][1]);
        }
        __syncthreads();
    }

#pragma unroll
    for (int nt = 0; nt < 8; nt++) {
        int n = n0 + wn * 64 + nt * 8 + t4 * 2;
        int g = n >> 10, j = n & 1023;
        const float* bias = (g == 0) ? bf : (g == 1) ? bi : (g == 2) ? bc : bo;
        float b0 = bias[j], b1 = bias[j + 1];
#pragma unroll
        for (int mt = 0; mt < 2; mt++) {
            int m = m0 + wm * 32 + mt * 16 + gid;
            *(__half2*)&g_gx[(size_t)m * NG + n]       = __floats2half2_rn(acc[mt][nt][0] + b0, acc[mt][nt][1] + b1);
            *(__half2*)&g_gx[(size_t)(m + 8) * NG + n] = __floats2half2_rn(acc[mt][nt][2] + b0, acc[mt][nt][3] + b1);
        }
    }
}

// ---------------- persistent scan: warp-specialized copy pipeline -----------
// 128 blocks x 544 thr. Warps 0-15 compute (R10 layout: 2kg x 4m x 2n);
// warp 16 lane 0 = copy engine. Copy engine walks s = t*8 + c, gated by
// per-buffer empty mbarriers (from compute) and per-chunk producer counters.
// Reduce scratch is a dedicated region (buffers stay live for copy-ahead).
#define HS_LD 136
#define CHKB  (64 * HS_LD * 2)       // 17408 bytes per chunk
#define WS_LD 1032
#define WS_HALFS (64 * WS_LD)
#define WS_BYTES (WS_HALFS * 2)      // 132096
#define HB_OFF   WS_BYTES
#define RED_OFF  (WS_BYTES + 4 * CHKB)      // 201728
#define SCAN_SMEM (RED_OFF + 256 * 20 * 4)  // 222208

__global__ __launch_bounds__(SCAN_THREADS, 1) void k_scan(float* __restrict__ out) {
    extern __shared__ __half sm[];
    __half* ws = sm;                                   // [64][WS_LD], row = g*16+jl
    __half* hs = sm + WS_HALFS;                        // 4 ring buffers [64][HS_LD]
    float*  red = (float*)((char*)sm + RED_OFF);       // 256 x 20 floats
    __shared__ __align__(8) uint64_t s_full[4];
    __shared__ __align__(8) uint64_t s_free[4];

    const int tid  = threadIdx.x;
    const int w    = tid >> 5;
    const int lane = tid & 31;

    const int bid   = blockIdx.x;
    const int mhalf = bid & 1;
    const int jb    = bid >> 1;
    const int j0    = jb * 16;
    const int my_cnt = ((jb >> 3) << 1) | mhalf;       // counter this block publishes

    const uint32_t hs_base = smem_u32(hs);
    const uint32_t ws_base = smem_u32(ws);
    uint32_t fullb[4], freeb[4];
#pragma unroll
    for (int i = 0; i < 4; i++) { fullb[i] = smem_u32(&s_full[i]); freeb[i] = smem_u32(&s_free[i]); }
    if (tid == 0) {
#pragma unroll
        for (int i = 0; i < 4; i++) { mbar_init(fullb[i], 1); mbar_init(freeb[i], 1); }
        fence_pa();
    }

    // ---- Wh slice once (compute threads only): row r = g*16+jl ----
    if (tid < 512) {
#pragma unroll 4
        for (int i = 0; i < 16; i++) {
            int cid = tid + i * 512;
            int r = cid >> 7, ch = cid & 127;
            int g = r >> 4, jl = r & 15;
            *(uint4*)&ws[r * WS_LD + ch * 8] =
                *(const uint4*)&g_Wh[(size_t)(g * H_ + j0 + jl) * H_ + ch * 8];
        }
    }
    __syncthreads();    // all 544: mbars ready, ws ready

    // ================= copy engine: warp 16 =================
    if (tid >= 512) {
        if (lane == 0) {
#pragma unroll 1
            for (int s = 0; s < T_ * 8; s++) {
                const int b = s & 3, t = s >> 3, c = s & 7, sq = s >> 2;
                if (s >= 4) mbar_wait(freeb[b], (uint32_t)((sq & 1) ^ 1));
                while (ld_acquire_gpu(&g_cnt[(c << 1) | mhalf]) < 8 * t) {}
                mbar_expect_tx(fullb[b], CHKB);
                bulk_g2s(hs_base + (uint32_t)(b * CHKB), &g_hk[t & 1][c][mhalf * 64][0], CHKB, fullb[b]);
            }
        }
        return;    // lanes 1-31 exit immediately; lane 0 exits after loop
    }

    // ================= compute warps 0-15 =================
    const int kg   = w >> 3;         // group 0/1
    const int ww   = w & 7;
    const int wm   = ww >> 1;        // 0..3 m-tile
    const int wn   = ww & 1;         // 0..1 j-half
    const int gid  = lane >> 2;
    const int t4   = lane & 3;

    const int a_row = wm * 16 + ((lane >> 3) & 1) * 8 + (lane & 7);
    const uint32_t a_lane_off = (uint32_t)((a_row * HS_LD + (lane >> 4) * 8) * 2);
    const uint32_t b_lane0 = ws_base + (uint32_t)(((((lane >> 4) + 0) * 16 + wn * 8 + (lane & 7)) * WS_LD
                                                   + ((lane >> 3) & 1) * 8) * 2);
    const uint32_t b_lane1 = ws_base + (uint32_t)(((((lane >> 4) + 2) * 16 + wn * 8 + (lane & 7)) * WS_LD
                                                   + ((lane >> 3) & 1) * 8) * 2);

    const int my_r = wm * 16 + gid;
    const int my_j = j0 + wn * 8 + t4 * 2;

    float cst[4] = {0.f, 0.f, 0.f, 0.f};    // kg0 warps only

    for (int t = 0; t < T_; t++) {
        const int hbuf = t & 1;

        // gx prefetch (epilogue threads; g_gx precomputed by k_gx)
        uint4 gq[8];
        if (tid < 256) {
            const __half* gp = &g_gx[((size_t)t * B_ + mhalf * 64 + my_r) * NG + my_j];
#pragma unroll
            for (int g = 0; g < 4; g++) {
                gq[g]     = __ldg((const uint4*)((const char*)gp + (size_t)g * H_ * 2 - (my_j & 7) * 2));
                gq[4 + g] = __ldg((const uint4*)((const char*)(gp + 8 * NG) + (size_t)g * H_ * 2 - (my_j & 7) * 2));
            }
        }

        float acc[4][4];
#pragma unroll
        for (int g = 0; g < 4; g++)
#pragma unroll
            for (int e = 0; e < 4; e++) acc[g][e] = 0.f;

        // ---- group-local pipeline: 4 chunks, 2 buffers ----
#pragma unroll
        for (int i = 0; i < 4; i++) {
            const int c = kg + 2 * i;                 // my chunk
            const int b = kg + ((i & 1) << 1);        // its buffer (= c&3)
            mbar_wait(fullb[b], (uint32_t)(i >> 1));  // parity (c>>2)&1, step-invariant

            const uint32_t aA  = hs_base + (uint32_t)(b * CHKB) + a_lane_off;
            const uint32_t aB0 = b_lane0 + (uint32_t)(c * 256);
            const uint32_t aB1 = b_lane1 + (uint32_t)(c * 256);
#pragma unroll
            for (int ks = 0; ks < 8; ks++) {
                uint32_t a[4], b01[4], b23[4];
                ldsm_x4(a,   aA  + ks * 32);
                ldsm_x4(b01, aB0 + ks * 32);
                ldsm_x4(b23, aB1 + ks * 32);
                mma16816(acc[0], a, b01[0], b01[1]);
                mma16816(acc[1], a, b01[2], b01[3]);
                mma16816(acc[2], a, b23[0], b23[1]);
                mma16816(acc[3], a, b23[2], b23[3]);
            }
            // group-local barrier: my 8 warps done reading buffer b
            asm volatile("bar.sync %0, 256;" :: "r"(kg + 1) : "memory");
            if (ww == 0 && lane == 0) mbar_arrive(freeb[b]);   // buffer free for copy engine
        }

        // ---- merge k-halves via dedicated scratch (stride 20 floats) ----
        const int rb = (ww * 32 + lane) * 20;
        if (kg == 1) {
#pragma unroll
            for (int g = 0; g < 4; g++)
                *(float4*)&red[rb + g * 4] = make_float4(acc[g][0], acc[g][1], acc[g][2], acc[g][3]);
        }
        asm volatile("bar.sync 3, 512;" ::: "memory");

        if (kg == 0) {
#pragma unroll
            for (int g = 0; g < 4; g++) {
                float4 v = *(const float4*)&red[rb + g * 4];
                acc[g][0] += v.x; acc[g][1] += v.y; acc[g][2] += v.z; acc[g][3] += v.w;
            }
            const int jc  = my_j >> 7;
            const int jcc = my_j & 127;
            const __half* gxh = (const __half*)gq;
            const int lo = my_j & 7;
#pragma unroll
            for (int rr = 0; rr < 2; rr++) {
                const int b_row = mhalf * 64 + my_r + rr * 8;
                float hres[2];
#pragma unroll
                for (int cc = 0; cc < 2; cc++) {
                    const int ai = rr * 2 + cc;
                    float pf = acc[0][ai] + __half2float(gxh[(rr * 4 + 0) * 8 + lo + cc]);
                    float pi = acc[1][ai] + __half2float(gxh[(rr * 4 + 1) * 8 + lo + cc]);
                    float pc = acc[2][ai] + __half2float(gxh[(rr * 4 + 2) * 8 + lo + cc]);
                    float po = acc[3][ai] + __half2float(gxh[(rr * 4 + 3) * 8 + lo + cc]);
                    float f = sigm(pf), ii = sigm(pi), ct = tanh_fast(pc), o = sigm(po);
                    float cn = f * cst[ai] + ii * ct;
                    cst[ai] = cn;
                    hres[cc] = o * tanh_fast(cn);
                }
                *(float2*)&out[((size_t)t * B_ + b_row) * H_ + my_j] = make_float2(hres[0], hres[1]);
                *(__half2*)&g_hk[hbuf ^ 1][jc][b_row][jcc] = __floats2half2_rn(hres[0], hres[1]);
            }
        }

        asm volatile("bar.sync 3, 512;" ::: "memory");
        if (tid == 0) red_release_add(&g_cnt[my_cnt], 1);
    }
}

// ---------------- launch ----------------------------------------------------
extern "C" void kernel_launch(void* const* d_in, const int* in_sizes, int n_in,
                              void* d_out, int out_size) {
    const float* x  = (const float*)d_in[0];
    const float* Wf = (const float*)d_in[1];
    const float* bf = (const float*)d_in[2];
    const float* Wi = (const float*)d_in[3];
    const float* bi = (const float*)d_in[4];
    const float* Wc = (const float*)d_in[5];
    const float* bc = (const float*)d_in[6];
    const float* Wo = (const float*)d_in[7];
    const float* bo = (const float*)d_in[8];
    float* out = (float*)d_out;

    cudaFuncSetAttribute(k_scan, cudaFuncAttributeMaxDynamicSharedMemorySize, SCAN_SMEM);

    {
        size_t total = (size_t)NG * KZ;
        k_prep_weights<<<(int)((total + 255) / 256), 256>>>(Wf, Wi, Wc, Wo);
    }
    {
        size_t total = (size_t)T_ * B_ * I_;
        k_convert_x<<<(int)((total + 255) / 256), 256>>>(x);
    }
    k_gx<<<dim3(NG / 128, (T_ * B_) / 128), 256>>>(bf, bi, bc, bo);

    k_scan<<<SCAN_BLOCKS, SCAN_THREADS, SCAN_SMEM>>>(out);
}

// round 17
// speedup vs baseline: 2.2165x; 1.0966x over previous
#include <cuda_runtime.h>
#include <cuda_fp16.h>
#include <cstdint>

#define T_  512
#define B_  128
#define I_  512
#define H_  1024
#define NG  4096
#define KZ  1536
#define SCAN_BLOCKS  128
#define SCAN_THREADS 512

__device__ __half g_xh[(size_t)T_ * B_ * I_];
__device__ __half g_gx[(size_t)T_ * B_ * NG];
__device__ __half g_Wh[(size_t)NG * H_];
__device__ __half g_Wx[(size_t)NG * I_];
// h ping-pong, k-chunked + padded rows: [buf][kchunk][row][136]
__device__ __align__(1024) __half g_hk[2][8][128][136];
__device__ int g_done[SCAN_BLOCKS];

__device__ __forceinline__ float sigm(float x) { return 1.0f / (1.0f + __expf(-x)); }
__device__ __forceinline__ float tanh_fast(float x) {
    float e = __expf(-2.0f * fabsf(x));
    return copysignf((1.0f - e) / (1.0f + e), x);
}
__device__ __forceinline__ void mma16816(float* d, const uint32_t* a, uint32_t b0, uint32_t b1) {
    asm volatile(
        "mma.sync.aligned.m16n8k16.row.col.f32.f16.f16.f32 "
        "{%0,%1,%2,%3}, {%4,%5,%6,%7}, {%8,%9}, {%0,%1,%2,%3};\n"
        : "+f"(d[0]), "+f"(d[1]), "+f"(d[2]), "+f"(d[3])
        : "r"(a[0]), "r"(a[1]), "r"(a[2]), "r"(a[3]), "r"(b0), "r"(b1));
}
__device__ __forceinline__ void ldsm_x4(uint32_t* r, uint32_t addr) {
    asm volatile("ldmatrix.sync.aligned.m8n8.x4.shared.b16 {%0,%1,%2,%3}, [%4];"
                 : "=r"(r[0]), "=r"(r[1]), "=r"(r[2]), "=r"(r[3]) : "r"(addr));
}
__device__ __forceinline__ int ld_acquire_gpu(const int* p) {
    int v; asm volatile("ld.acquire.gpu.b32 %0, [%1];\n" : "=r"(v) : "l"(p) : "memory"); return v;
}
__device__ __forceinline__ void st_release_gpu(int* p, int v) {
    asm volatile("st.release.gpu.global.b32 [%0], %1;\n" :: "l"(p), "r"(v) : "memory");
}
__device__ __forceinline__ uint32_t smem_u32(const void* p) {
    uint32_t a; asm("{ .reg .u64 t; cvta.to.shared.u64 t, %1; cvt.u32.u64 %0, t; }" : "=r"(a) : "l"(p)); return a;
}
__device__ __forceinline__ void mbar_init(uint32_t m, uint32_t c) {
    asm volatile("mbarrier.init.shared.b64 [%0], %1;" :: "r"(m), "r"(c) : "memory");
}
__device__ __forceinline__ void mbar_expect_tx(uint32_t m, uint32_t bytes) {
    asm volatile("mbarrier.arrive.expect_tx.shared.b64 _, [%0], %1;" :: "r"(m), "r"(bytes) : "memory");
}
__device__ __forceinline__ void mbar_wait(uint32_t m, uint32_t par) {
    asm volatile(
        "{\n\t.reg .pred P1;\n\t"
        "WL_%=:\n\t"
        "mbarrier.try_wait.parity.shared.b64 P1, [%0], %1;\n\t"
        "@P1 bra.uni WD_%=;\n\tbra.uni WL_%=;\n\tWD_%=:\n\t}"
        :: "r"(m), "r"(par) : "memory");
}
__device__ __forceinline__ void bulk_g2s(uint32_t dst, const void* src, uint32_t bytes, uint32_t mbar) {
    asm volatile("cp.async.bulk.shared::cluster.global.mbarrier::complete_tx::bytes [%0], [%1], %2, [%3];"
                 :: "r"(dst), "l"(src), "r"(bytes), "r"(mbar) : "memory");
}
__device__ __forceinline__ void cp_async16(uint32_t s, const void* g) {
    asm volatile("cp.async.cg.shared.global [%0], [%1], 16;\n" :: "r"(s), "l"(g));
}
__device__ __forceinline__ void fence_pa() { asm volatile("fence.proxy.async.shared::cta;" ::: "memory"); }

// ---------------- merged prep: weights + x-convert + state init -------------
__global__ void k_prep(const float* __restrict__ x,
                       const float* __restrict__ Wf, const float* __restrict__ Wi,
                       const float* __restrict__ Wc, const float* __restrict__ Wo) {
    size_t idx = (size_t)blockIdx.x * blockDim.x + threadIdx.x;

    // weights: scalar split, 6.29M elements
    if (idx < (size_t)NG * KZ) {
        int n = (int)(idx / KZ), k = (int)(idx % KZ);
        int g = n >> 10, j = n & 1023;
        const float* W = (g == 0) ? Wf : (g == 1) ? Wi : (g == 2) ? Wc : Wo;
        float v = W[(size_t)j * KZ + k];
        if (k < H_) g_Wh[(size_t)n * H_ + k]        = __float2half(v);
        else        g_Wx[(size_t)n * I_ + (k - H_)] = __float2half(v);
    }

    // x convert: 8 elements per thread (2x float4 -> 1x uint4 of halfs)
    if (idx < (size_t)T_ * B_ * I_ / 8) {
        const float4* xp = (const float4*)(x + idx * 8);
        float4 v0 = __ldg(xp), v1 = __ldg(xp + 1);
        __half2 h0 = __floats2half2_rn(v0.x, v0.y);
        __half2 h1 = __floats2half2_rn(v0.z, v0.w);
        __half2 h2 = __floats2half2_rn(v1.x, v1.y);
        __half2 h3 = __floats2half2_rn(v1.z, v1.w);
        uint4 o;
        o.x = *(uint32_t*)&h0; o.y = *(uint32_t*)&h1;
        o.z = *(uint32_t*)&h2; o.w = *(uint32_t*)&h3;
        *(uint4*)&g_xh[idx * 8] = o;
    }

    // h state init: 278528 halfs, 8 per thread
    if (idx < (size_t)2 * 8 * 128 * 136 / 8) {
        uint4 z = make_uint4(0, 0, 0, 0);
        *(uint4*)&((__half*)g_hk)[idx * 8] = z;
    }
    if (idx < SCAN_BLOCKS) g_done[idx] = 0;
}

// ---------------- gx GEMM: cp.async double-buffered (R14, passing) ----------
__global__ __launch_bounds__(256) void k_gx(const float* __restrict__ bf, const float* __restrict__ bi,
                                            const float* __restrict__ bc, const float* __restrict__ bo) {
    __shared__ __half As[2][128][40];
    __shared__ __half Bs[2][128][40];
    const int m0 = blockIdx.y * 128, n0 = blockIdx.x * 128;
    const int tid = threadIdx.x, w = tid >> 5, lane = tid & 31;
    const int gid = lane >> 2, t4 = lane & 3, wm = w >> 1, wn = w & 1;

    const uint32_t as_base = smem_u32(&As[0][0][0]);
    const uint32_t bs_base = smem_u32(&Bs[0][0][0]);
    const uint32_t buf_stride = 128 * 40 * 2;

    float acc[2][8][4];
#pragma unroll
    for (int mt = 0; mt < 2; mt++)
#pragma unroll
        for (int nt = 0; nt < 8; nt++)
#pragma unroll
            for (int e = 0; e < 4; e++) acc[mt][nt][e] = 0.0f;

    const int r0 = tid >> 2, c0 = tid & 3;
    const int r1 = (tid + 256) >> 2, c1 = (tid + 256) & 3;

    cp_async16(as_base + (uint32_t)((r0 * 40 + c0 * 8) * 2), &g_xh[(size_t)(m0 + r0) * I_ + c0 * 8]);
    cp_async16(as_base + (uint32_t)((r1 * 40 + c1 * 8) * 2), &g_xh[(size_t)(m0 + r1) * I_ + c1 * 8]);
    cp_async16(bs_base + (uint32_t)((r0 * 40 + c0 * 8) * 2), &g_Wx[(size_t)(n0 + r0) * I_ + c0 * 8]);
    cp_async16(bs_base + (uint32_t)((r1 * 40 + c1 * 8) * 2), &g_Wx[(size_t)(n0 + r1) * I_ + c1 * 8]);
    asm volatile("cp.async.commit_group;\n");

#pragma unroll 1
    for (int s = 0; s < 16; s++) {
        if (s < 15) {
            const int kb = (s + 1) * 32;
            const uint32_t bo_ = (uint32_t)(((s + 1) & 1) * buf_stride);
            cp_async16(as_base + bo_ + (uint32_t)((r0 * 40 + c0 * 8) * 2), &g_xh[(size_t)(m0 + r0) * I_ + kb + c0 * 8]);
            cp_async16(as_base + bo_ + (uint32_t)((r1 * 40 + c1 * 8) * 2), &g_xh[(size_t)(m0 + r1) * I_ + kb + c1 * 8]);
            cp_async16(bs_base + bo_ + (uint32_t)((r0 * 40 + c0 * 8) * 2), &g_Wx[(size_t)(n0 + r0) * I_ + kb + c0 * 8]);
            cp_async16(bs_base + bo_ + (uint32_t)((r1 * 40 + c1 * 8) * 2), &g_Wx[(size_t)(n0 + r1) * I_ + kb + c1 * 8]);
            asm volatile("cp.async.commit_group;\n");
            asm volatile("cp.async.wait_group 1;\n");
        } else {
            asm volatile("cp.async.wait_group 0;\n");
        }
        __syncthreads();

        const int bi_ = s & 1;
#pragma unroll
        for (int ks = 0; ks < 2; ks++) {
            const int ko = ks * 16;
            uint32_t a[2][4], b[8][2];
#pragma unroll
            for (int mt = 0; mt < 2; mt++) {
                int r = wm * 32 + mt * 16 + gid;
                a[mt][0] = *(const uint32_t*)&As[bi_][r][ko + t4 * 2];
                a[mt][1] = *(const uint32_t*)&As[bi_][r + 8][ko + t4 * 2];
                a[mt][2] = *(const uint32_t*)&As[bi_][r][ko + t4 * 2 + 8];
                a[mt][3] = *(const uint32_t*)&As[bi_][r + 8][ko + t4 * 2 + 8];
            }
#pragma unroll
            for (int nt = 0; nt < 8; nt++) {
                int c = wn * 64 + nt * 8 + gid;
                b[nt][0] = *(const uint32_t*)&Bs[bi_][c][ko + t4 * 2];
                b[nt][1] = *(const uint32_t*)&Bs[bi_][c][ko + t4 * 2 + 8];
            }
#pragma unroll
            for (int mt = 0; mt < 2; mt++)
#pragma unroll
                for (int nt = 0; nt < 8; nt++)
                    mma16816(acc[mt][nt], a[mt], b[nt][0], b[nt][1]);
        }
        __syncthreads();
    }

#pragma unroll
    for (int nt = 0; nt < 8; nt++) {
        int n = n0 + wn * 64 + nt * 8 + t4 * 2;
        int g = n >> 10, j = n & 1023;
        const float* bias = (g == 0) ? bf : (g == 1) ? bi : (g == 2) ? bc : bo;
        float b0 = bias[j], b1 = bias[j + 1];
#pragma unroll
        for (int mt = 0; mt < 2; mt++) {
            int m = m0 + wm * 32 + mt * 16 + gid;
            *(__half2*)&g_gx[(size_t)m * NG + n]       = __floats2half2_rn(acc[mt][nt][0] + b0, acc[mt][nt][1] + b1);
            *(__half2*)&g_gx[(size_t)(m + 8) * NG + n] = __floats2half2_rn(acc[mt][nt][2] + b0, acc[mt][nt][3] + b1);
        }
    }
}

// ---------------- persistent LSTM scan: R14/R10 verbatim --------------------
#define HS_LD 136
#define CHKB  (64 * HS_LD * 2)       // 17408 bytes per chunk
#define WS_LD 1032
#define WS_HALFS (64 * WS_LD)
#define WS_BYTES (WS_HALFS * 2)      // 132096
#define SCAN_SMEM (WS_BYTES + 4 * CHKB)

__global__ __launch_bounds__(SCAN_THREADS, 1) void k_scan(float* __restrict__ out) {
    extern __shared__ __half sm[];
    __half* ws = sm;                 // [64][WS_LD], row = g*16 + jl
    __half* hs = sm + WS_HALFS;      // 4 buffers [64][HS_LD]; reused as reduce scratch
    __shared__ __align__(8) uint64_t s_mbar[4];

    const int tid  = threadIdx.x;
    const int w    = tid >> 5;
    const int lane = tid & 31;
    const int kg   = w >> 3;
    const int ww   = w & 7;
    const int wm   = ww >> 1;
    const int wn   = ww & 1;
    const int gid  = lane >> 2;
    const int t4   = lane & 3;

    const int bid   = blockIdx.x;
    const int mhalf = bid & 1;
    const int jb    = bid >> 1;
    const int j0    = jb * 16;

#pragma unroll 4
    for (int i = 0; i < 16; i++) {
        int cid = tid + i * SCAN_THREADS;
        int r = cid >> 7, ch = cid & 127;
        int g = r >> 4, jl = r & 15;
        *(uint4*)&ws[r * WS_LD + ch * 8] =
            *(const uint4*)&g_Wh[(size_t)(g * H_ + j0 + jl) * H_ + ch * 8];
    }

    const uint32_t hs_base = smem_u32(hs);
    const uint32_t ws_base = smem_u32(ws);
    uint32_t mb[4];
#pragma unroll
    for (int i = 0; i < 4; i++) mb[i] = smem_u32(&s_mbar[i]);
    if (tid == 0) {
#pragma unroll
        for (int i = 0; i < 4; i++) mbar_init(mb[i], 1);
        fence_pa();
    }
    __syncthreads();

    const int a_row = wm * 16 + ((lane >> 3) & 1) * 8 + (lane & 7);
    const uint32_t a_lane_off = (uint32_t)((a_row * HS_LD + (lane >> 4) * 8) * 2);
    const uint32_t b_lane0 = ws_base + (uint32_t)(((((lane >> 4) + 0) * 16 + wn * 8 + (lane & 7)) * WS_LD
                                                   + ((lane >> 3) & 1) * 8) * 2);
    const uint32_t b_lane1 = ws_base + (uint32_t)(((((lane >> 4) + 2) * 16 + wn * 8 + (lane & 7)) * WS_LD
                                                   + ((lane >> 3) & 1) * 8) * 2);

    const int my_r = wm * 16 + gid;
    const int my_j = j0 + wn * 8 + t4 * 2;

    float cst[4] = {0.f, 0.f, 0.f, 0.f};

    for (int t = 0; t < T_; t++) {
        const int hbuf = t & 1;

        uint4 gq[8];
        if (tid < 256) {
            const __half* gp = &g_gx[((size_t)t * B_ + mhalf * 64 + my_r) * NG + my_j];
#pragma unroll
            for (int g = 0; g < 4; g++) {
                gq[g]     = __ldg((const uint4*)((const char*)gp + (size_t)g * H_ * 2 - (my_j & 7) * 2));
                gq[4 + g] = __ldg((const uint4*)((const char*)(gp + 8 * NG) + (size_t)g * H_ * 2 - (my_j & 7) * 2));
            }
        }

        if (t > 0) {
            if (tid < 64) {
                const int* p = &g_done[mhalf + 2 * tid];
                while (ld_acquire_gpu(p) < t) {}
            }
            __syncthreads();
        }

        if (tid == 0) {
#pragma unroll
            for (int c = 0; c < 4; c++) {
                mbar_expect_tx(mb[c], CHKB);
                bulk_g2s(hs_base + (uint32_t)(c * CHKB), &g_hk[hbuf][c][mhalf * 64][0], CHKB, mb[c]);
            }
        }

        float acc[4][4];
#pragma unroll
        for (int g = 0; g < 4; g++)
#pragma unroll
            for (int e = 0; e < 4; e++) acc[g][e] = 0.f;

#pragma unroll
        for (int i = 0; i < 4; i++) {
            const int c = kg + 2 * i;
            const int b = kg + ((i & 1) << 1);
            mbar_wait(mb[b], (uint32_t)(i >> 1));

            const uint32_t aA  = hs_base + (uint32_t)(b * CHKB) + a_lane_off;
            const uint32_t aB0 = b_lane0 + (uint32_t)(c * 256);
            const uint32_t aB1 = b_lane1 + (uint32_t)(c * 256);
#pragma unroll
            for (int ks = 0; ks < 8; ks++) {
                uint32_t a[4], b01[4], b23[4];
                ldsm_x4(a,   aA  + ks * 32);
                ldsm_x4(b01, aB0 + ks * 32);
                ldsm_x4(b23, aB1 + ks * 32);
                mma16816(acc[0], a, b01[0], b01[1]);
                mma16816(acc[1], a, b01[2], b01[3]);
                mma16816(acc[2], a, b23[0], b23[1]);
                mma16816(acc[3], a, b23[2], b23[3]);
            }
            asm volatile("bar.sync %0, 256;" :: "r"(kg + 1) : "memory");
            if (i < 2 && ww == 0 && lane == 0) {
                mbar_expect_tx(mb[b], CHKB);
                bulk_g2s(hs_base + (uint32_t)(b * CHKB),
                         &g_hk[hbuf][c + 4][mhalf * 64][0], CHKB, mb[b]);
            }
        }
        __syncthreads();

        float* red = (float*)hs;
        const int rb = (ww * 32 + lane) * 20;
        if (kg == 1) {
#pragma unroll
            for (int g = 0; g < 4; g++)
                *(float4*)&red[rb + g * 4] = make_float4(acc[g][0], acc[g][1], acc[g][2], acc[g][3]);
        }
        __syncthreads();

        if (kg == 0) {
#pragma unroll
            for (int g = 0; g < 4; g++) {
                float4 v = *(const float4*)&red[rb + g * 4];
                acc[g][0] += v.x; acc[g][1] += v.y; acc[g][2] += v.z; acc[g][3] += v.w;
            }
            const int jc  = my_j >> 7;
            const int jcc = my_j & 127;
            const __half* gxh = (const __half*)gq;
            const int lo = my_j & 7;
#pragma unroll
            for (int rr = 0; rr < 2; rr++) {
                const int b_row = mhalf * 64 + my_r + rr * 8;
                float hres[2];
#pragma unroll
                for (int cc = 0; cc < 2; cc++) {
                    const int ai = rr * 2 + cc;
                    float pf = acc[0][ai] + __half2float(gxh[(rr * 4 + 0) * 8 + lo + cc]);
                    float pi = acc[1][ai] + __half2float(gxh[(rr * 4 + 1) * 8 + lo + cc]);
                    float pc = acc[2][ai] + __half2float(gxh[(rr * 4 + 2) * 8 + lo + cc]);
                    float po = acc[3][ai] + __half2float(gxh[(rr * 4 + 3) * 8 + lo + cc]);
                    float f = sigm(pf), ii = sigm(pi), ct = tanh_fast(pc), o = sigm(po);
                    float cn = f * cst[ai] + ii * ct;
                    cst[ai] = cn;
                    hres[cc] = o * tanh_fast(cn);
                }
                *(float2*)&out[((size_t)t * B_ + b_row) * H_ + my_j] = make_float2(hres[0], hres[1]);
                *(__half2*)&g_hk[hbuf ^ 1][jc][b_row][jcc] = __floats2half2_rn(hres[0], hres[1]);
            }
        }

        __syncthreads();
        if (tid == 0) st_release_gpu(&g_done[bid], t + 1);
    }
}

// ---------------- launch ----------------------------------------------------
extern "C" void kernel_launch(void* const* d_in, const int* in_sizes, int n_in,
                              void* d_out, int out_size) {
    const float* x  = (const float*)d_in[0];
    const float* Wf = (const float*)d_in[1];
    const float* bf = (const float*)d_in[2];
    const float* Wi = (const float*)d_in[3];
    const float* bi = (const float*)d_in[4];
    const float* Wc = (const float*)d_in[5];
    const float* bc = (const float*)d_in[6];
    const float* Wo = (const float*)d_in[7];
    const float* bo = (const float*)d_in[8];
    float* out = (float*)d_out;

    cudaFuncSetAttribute(k_scan, cudaFuncAttributeMaxDynamicSharedMemorySize, SCAN_SMEM);

    {
        size_t total = (size_t)NG * KZ;     // 6.29M threads covers all sub-tasks
        k_prep<<<(int)((total + 255) / 256), 256>>>(x, Wf, Wi, Wc, Wo);
    }
    k_gx<<<dim3(NG / 128, (T_ * B_) / 128), 256>>>(bf, bi, bc, bo);

    k_scan<<<SCAN_BLOCKS, SCAN_THREADS, SCAN_SMEM>>>(out);
}